// round 2
// baseline (speedup 1.0000x reference)
#include <cuda_runtime.h>
#include <math.h>

#define NB 4
#define NS 2048
#define NE 1024
#define ND 128

// Scratch (device globals: allocation-free per harness rules)
__device__ float g_q[NB * NS * ND];
__device__ float g_k[NB * NS * ND];
__device__ float g_v[NB * NS * ND];
__device__ float g_s[(size_t)NB * NS * NS];   // 64 MB score/prob matrix

// ---------------------------------------------------------------------------
// Kernel 1: fused QKV projection.  [8192,1024] x [1024,128] + bias, x3
// BM=64, BN=128, BK=8, 256 threads, 8x4 microtile per thread.
// blockIdx.y selects q/k/v.
// ---------------------------------------------------------------------------
__global__ __launch_bounds__(256) void qkv_kernel(
    const float* __restrict__ x,
    const float* __restrict__ wq, const float* __restrict__ bq,
    const float* __restrict__ wk, const float* __restrict__ bk,
    const float* __restrict__ wv, const float* __restrict__ bv)
{
    const float *w, *bias;
    float *outp;
    if (blockIdx.y == 0)      { w = wq; bias = bq; outp = g_q; }
    else if (blockIdx.y == 1) { w = wk; bias = bk; outp = g_k; }
    else                      { w = wv; bias = bv; outp = g_v; }

    __shared__ __align__(16) float As[8][64];
    __shared__ __align__(16) float Bs[8][128];

    const int tid  = threadIdx.x;
    const int m0   = blockIdx.x * 64;
    const int tr   = tid >> 5;          // 0..7  : row group (warp-uniform)
    const int tc   = tid & 31;          // 0..31 : col group
    const int arow = tid >> 2;          // 0..63
    const int acol = (tid & 3) * 2;     // 0,2,4,6
    const int brow = tid >> 5;          // 0..7
    const int bcol = (tid & 31) * 4;    // 0..124

    float acc[8][4];
    #pragma unroll
    for (int i = 0; i < 8; i++)
        #pragma unroll
        for (int j = 0; j < 4; j++) acc[i][j] = 0.f;

    for (int k0 = 0; k0 < NE; k0 += 8) {
        float2 a2 = *(const float2*)(x + (size_t)(m0 + arow) * NE + k0 + acol);
        float4 b4 = *(const float4*)(w + (size_t)(k0 + brow) * ND + bcol);
        __syncthreads();
        As[acol    ][arow] = a2.x;
        As[acol + 1][arow] = a2.y;
        *(float4*)&Bs[brow][bcol] = b4;
        __syncthreads();
        #pragma unroll
        for (int k = 0; k < 8; k++) {
            float a[8];
            #pragma unroll
            for (int i = 0; i < 8; i++) a[i] = As[k][tr * 8 + i];  // warp-broadcast
            float4 bb = *(const float4*)&Bs[k][tc * 4];
            #pragma unroll
            for (int i = 0; i < 8; i++) {
                acc[i][0] = fmaf(a[i], bb.x, acc[i][0]);
                acc[i][1] = fmaf(a[i], bb.y, acc[i][1]);
                acc[i][2] = fmaf(a[i], bb.z, acc[i][2]);
                acc[i][3] = fmaf(a[i], bb.w, acc[i][3]);
            }
        }
    }

    float4 bia = *(const float4*)(bias + tc * 4);
    #pragma unroll
    for (int i = 0; i < 8; i++) {
        float4 r;
        r.x = acc[i][0] + bia.x;
        r.y = acc[i][1] + bia.y;
        r.z = acc[i][2] + bia.z;
        r.w = acc[i][3] + bia.w;
        *(float4*)(outp + (size_t)(m0 + tr * 8 + i) * ND + tc * 4) = r;
    }
}

// Triangular block decode: bidx in [0, 136) -> (bi, bj), bj <= bi, bi in [0,16)
__device__ __forceinline__ void tri_decode(int bidx, int& bi, int& bj)
{
    int r = (int)((sqrtf(8.f * bidx + 1.f) - 1.f) * 0.5f);
    while ((r + 1) * (r + 2) / 2 <= bidx) r++;
    while (r * (r + 1) / 2 > bidx) r--;
    bi = r;
    bj = bidx - r * (r + 1) / 2;
}

// ---------------------------------------------------------------------------
// Kernel 2: scores = (q . k^T) * scale, causal mask -> -inf.
// Lower-triangular 128x128 tiles only. 136 blocks x 4 batches.
// GEMM M=128 N=128 K=128, 256 threads, 8x8 microtile.
// ---------------------------------------------------------------------------
__global__ __launch_bounds__(256) void scores_kernel()
{
    int bi, bj;
    tri_decode(blockIdx.x, bi, bj);
    const int b  = blockIdx.y;
    const int i0 = bi * 128;
    const int j0 = bj * 128;

    const float* q  = g_q + (size_t)b * NS * ND;
    const float* km = g_k + (size_t)b * NS * ND;
    float* sout     = g_s + ((size_t)b << 22);

    __shared__ __align__(16) float As[8][128];
    __shared__ __align__(16) float Bs[8][128];

    const int tid  = threadIdx.x;
    const int row  = tid >> 1;          // 0..127
    const int half = tid & 1;
    const int tr   = tid >> 4;          // 0..15
    const int tc   = tid & 15;          // 0..15

    float acc[8][8];
    #pragma unroll
    for (int i = 0; i < 8; i++)
        #pragma unroll
        for (int j = 0; j < 8; j++) acc[i][j] = 0.f;

    for (int k0 = 0; k0 < ND; k0 += 8) {
        float4 a4 = *(const float4*)(q  + (size_t)(i0 + row) * ND + k0 + half * 4);
        float4 b4 = *(const float4*)(km + (size_t)(j0 + row) * ND + k0 + half * 4);
        __syncthreads();
        As[half * 4    ][row] = a4.x;
        As[half * 4 + 1][row] = a4.y;
        As[half * 4 + 2][row] = a4.z;
        As[half * 4 + 3][row] = a4.w;
        Bs[half * 4    ][row] = b4.x;
        Bs[half * 4 + 1][row] = b4.y;
        Bs[half * 4 + 2][row] = b4.z;
        Bs[half * 4 + 3][row] = b4.w;
        __syncthreads();
        #pragma unroll
        for (int k = 0; k < 8; k++) {
            float4 a0 = *(const float4*)&As[k][tr * 8];
            float4 a1 = *(const float4*)&As[k][tr * 8 + 4];
            float4 b0 = *(const float4*)&Bs[k][tc * 8];
            float4 b1 = *(const float4*)&Bs[k][tc * 8 + 4];
            float av[8] = {a0.x, a0.y, a0.z, a0.w, a1.x, a1.y, a1.z, a1.w};
            float bv[8] = {b0.x, b0.y, b0.z, b0.w, b1.x, b1.y, b1.z, b1.w};
            #pragma unroll
            for (int i = 0; i < 8; i++)
                #pragma unroll
                for (int j = 0; j < 8; j++)
                    acc[i][j] = fmaf(av[i], bv[j], acc[i][j]);
        }
    }

    const float scale = 0.08838834764831845f;   // 1/sqrt(128)
    #pragma unroll
    for (int i = 0; i < 8; i++) {
        const int gi = i0 + tr * 8 + i;
        #pragma unroll
        for (int j = 0; j < 8; j++) {
            const int gj = j0 + tc * 8 + j;
            sout[(size_t)gi * NS + gj] = (gj <= gi) ? acc[i][j] * scale : -INFINITY;
        }
    }
}

// ---------------------------------------------------------------------------
// Kernel 3: row softmax in place over padded length (next 128 multiple).
// Padded entries are -inf -> exp()=0 -> written as exact zeros (consumed by pv).
// ---------------------------------------------------------------------------
__global__ __launch_bounds__(256) void softmax_kernel()
{
    __shared__ float buf[2048];
    __shared__ float red[8];

    const int r   = blockIdx.x;
    const int b   = r >> 11;
    const int i   = r & 2047;
    float* s      = g_s + ((size_t)b << 22) + (size_t)i * NS;
    const int Lp  = ((i >> 7) + 1) << 7;
    const int tid = threadIdx.x;
    const int lane = tid & 31, wid = tid >> 5;

    float m = -INFINITY;
    for (int j = tid; j < Lp; j += 256) {
        float v = s[j];
        buf[j] = v;
        m = fmaxf(m, v);
    }
    #pragma unroll
    for (int o = 16; o; o >>= 1) m = fmaxf(m, __shfl_xor_sync(0xffffffffu, m, o));
    if (lane == 0) red[wid] = m;
    __syncthreads();
    m = red[0];
    #pragma unroll
    for (int w = 1; w < 8; w++) m = fmaxf(m, red[w]);
    __syncthreads();

    float sum = 0.f;
    for (int j = tid; j < Lp; j += 256) {
        float e = expf(buf[j] - m);   // exp(-inf - m) == 0 handles padding
        buf[j] = e;
        sum += e;
    }
    #pragma unroll
    for (int o = 16; o; o >>= 1) sum += __shfl_xor_sync(0xffffffffu, sum, o);
    if (lane == 0) red[wid] = sum;
    __syncthreads();
    sum = red[0];
    #pragma unroll
    for (int w = 1; w < 8; w++) sum += red[w];

    const float inv = 1.f / sum;
    for (int j = tid; j < Lp; j += 256) s[j] = buf[j] * inv;
}

// ---------------------------------------------------------------------------
// Kernel 4: out += P[128x128 tile] . V[128x128].  Triangular block pairs,
// fp32 atomicAdd accumulation into d_out (zeroed beforehand).
// ---------------------------------------------------------------------------
__global__ __launch_bounds__(256) void pv_kernel(float* __restrict__ out)
{
    int bi, bj;
    tri_decode(blockIdx.x, bi, bj);
    const int b  = blockIdx.y;
    const int i0 = bi * 128;
    const int j0 = bj * 128;

    const float* p = g_s + ((size_t)b << 22);
    const float* v = g_v + (size_t)b * NS * ND;

    __shared__ __align__(16) float As[8][128];
    __shared__ __align__(16) float Bs[8][128];

    const int tid  = threadIdx.x;
    const int row  = tid >> 1;
    const int half = tid & 1;
    const int brow = tid >> 5;          // 0..7
    const int bcol = (tid & 31) * 4;
    const int tr   = tid >> 4;
    const int tc   = tid & 15;

    float acc[8][8];
    #pragma unroll
    for (int i = 0; i < 8; i++)
        #pragma unroll
        for (int j = 0; j < 8; j++) acc[i][j] = 0.f;

    for (int k0 = 0; k0 < 128; k0 += 8) {
        float4 a4 = *(const float4*)(p + (size_t)(i0 + row) * NS + j0 + k0 + half * 4);
        float4 b4 = *(const float4*)(v + (size_t)(j0 + k0 + brow) * ND + bcol);
        __syncthreads();
        As[half * 4    ][row] = a4.x;
        As[half * 4 + 1][row] = a4.y;
        As[half * 4 + 2][row] = a4.z;
        As[half * 4 + 3][row] = a4.w;
        *(float4*)&Bs[brow][bcol] = b4;
        __syncthreads();
        #pragma unroll
        for (int k = 0; k < 8; k++) {
            float4 a0 = *(const float4*)&As[k][tr * 8];
            float4 a1 = *(const float4*)&As[k][tr * 8 + 4];
            float4 b0 = *(const float4*)&Bs[k][tc * 8];
            float4 b1 = *(const float4*)&Bs[k][tc * 8 + 4];
            float av[8] = {a0.x, a0.y, a0.z, a0.w, a1.x, a1.y, a1.z, a1.w};
            float bv[8] = {b0.x, b0.y, b0.z, b0.w, b1.x, b1.y, b1.z, b1.w};
            #pragma unroll
            for (int i = 0; i < 8; i++)
                #pragma unroll
                for (int j = 0; j < 8; j++)
                    acc[i][j] = fmaf(av[i], bv[j], acc[i][j]);
        }
    }

    #pragma unroll
    for (int i = 0; i < 8; i++) {
        const int gi = i0 + tr * 8 + i;
        float* orow = out + ((size_t)(b * NS + gi)) * ND + tc * 8;
        #pragma unroll
        for (int j = 0; j < 8; j++)
            atomicAdd(orow + j, acc[i][j]);
    }
}

// ---------------------------------------------------------------------------
extern "C" void kernel_launch(void* const* d_in, const int* in_sizes, int n_in,
                              void* d_out, int out_size)
{
    const float* x  = (const float*)d_in[0];
    const float* wq = (const float*)d_in[1];
    const float* bq = (const float*)d_in[2];
    const float* wk = (const float*)d_in[3];
    const float* bk = (const float*)d_in[4];
    const float* wv = (const float*)d_in[5];
    const float* bv = (const float*)d_in[6];
    float* out = (float*)d_out;

    cudaMemsetAsync(out, 0, (size_t)out_size * sizeof(float));
    qkv_kernel<<<dim3((NB * NS) / 64, 3), 256>>>(x, wq, bq, wk, bk, wv, bv);
    scores_kernel<<<dim3(136, NB), 256>>>();
    softmax_kernel<<<NB * NS, 256>>>();
    pv_kernel<<<dim3(136, NB), 256>>>(out);
}

// round 5
// speedup vs baseline: 1.9614x; 1.9614x over previous
#include <cuda_runtime.h>
#include <cuda_bf16.h>
#include <stdint.h>
#include <math.h>

#define NB 4
#define NS 2048
#define NE 1024
#define ND 128
#define NTOK 8192

typedef __nv_bfloat16 bf;

// ---------------- device scratch (allocation-free) ----------------
__device__ float g_s [(size_t)NTOK * NS];            // 64 MB scores
__device__ bf g_Ph[(size_t)NTOK * NS];
__device__ bf g_Pl[(size_t)NTOK * NS];
__device__ bf g_qh[NTOK * ND], g_ql[NTOK * ND];
__device__ bf g_kh[NTOK * ND], g_kl[NTOK * ND];
__device__ bf g_vh[NTOK * ND], g_vl[NTOK * ND];      // [tok][d]
__device__ bf g_wh[3 * NE * ND], g_wl[3 * NE * ND];  // [mat][e][d]

// ---------------- helpers ----------------
__device__ __forceinline__ uint32_t s2u(const void* p) {
    uint32_t a;
    asm("{ .reg .u64 t; cvta.to.shared.u64 t, %1; cvt.u32.u64 %0, t; }" : "=r"(a) : "l"(p));
    return a;
}
__device__ __forceinline__ void ldsm4(uint32_t& r0, uint32_t& r1, uint32_t& r2, uint32_t& r3, uint32_t a) {
    asm volatile("ldmatrix.sync.aligned.m8n8.x4.shared.b16 {%0,%1,%2,%3}, [%4];"
        : "=r"(r0), "=r"(r1), "=r"(r2), "=r"(r3) : "r"(a));
}
__device__ __forceinline__ void ldsm4t(uint32_t& r0, uint32_t& r1, uint32_t& r2, uint32_t& r3, uint32_t a) {
    asm volatile("ldmatrix.sync.aligned.m8n8.x4.trans.shared.b16 {%0,%1,%2,%3}, [%4];"
        : "=r"(r0), "=r"(r1), "=r"(r2), "=r"(r3) : "r"(a));
}
__device__ __forceinline__ void mma16816(float* c,
    uint32_t a0, uint32_t a1, uint32_t a2, uint32_t a3, uint32_t b0, uint32_t b1) {
    asm volatile("mma.sync.aligned.m16n8k16.row.col.f32.bf16.bf16.f32 "
        "{%0,%1,%2,%3}, {%4,%5,%6,%7}, {%8,%9}, {%0,%1,%2,%3};"
        : "+f"(c[0]), "+f"(c[1]), "+f"(c[2]), "+f"(c[3])
        : "r"(a0), "r"(a1), "r"(a2), "r"(a3), "r"(b0), "r"(b1));
}
__device__ __forceinline__ void split2(float a, float b, uint32_t& hi, uint32_t& lo) {
    bf ha = __float2bfloat16(a), hb = __float2bfloat16(b);
    bf la = __float2bfloat16(a - __bfloat162float(ha));
    bf lb = __float2bfloat16(b - __bfloat162float(hb));
    __nv_bfloat162 H, L;
    H.x = ha; H.y = hb; L.x = la; L.y = lb;
    hi = *(uint32_t*)&H; lo = *(uint32_t*)&L;
}
__device__ __forceinline__ void tri_decode(int bidx, int& bi, int& bj) {
    int r = (int)((sqrtf(8.f * bidx + 1.f) - 1.f) * 0.5f);
    while ((r + 1) * (r + 2) / 2 <= bidx) r++;
    while (r * (r + 1) / 2 > bidx) r--;
    bi = r; bj = bidx - r * (r + 1) / 2;
}

// Warp-level GEMM over one K=32 chunk.
// A tiles [128][40] bf16 (hi/lo), padded row stride 80 B.
// TRANSB=0: B tile [128 n][40 k]   (col-major B, natural for K[tok][d])
// TRANSB=1: B tile [32 k][136 n]   (row-major K x N via ldmatrix.trans)
template<int TRANSB>
__device__ __forceinline__ void compute_chunk(
    float (*acc)[4], uint32_t Ah, uint32_t Al, uint32_t Bh, uint32_t Bl,
    int lane, int warpM, int warpN)
{
    const uint32_t arow  = warpM * 32 + (lane & 7) + ((lane >> 3) & 1) * 8;
    const uint32_t acolb = ((lane >> 4) & 1) * 16;
    #pragma unroll
    for (int ks = 0; ks < 2; ks++) {
        uint32_t ah[2][4], al2[2][4];
        #pragma unroll
        for (int m = 0; m < 2; m++) {
            uint32_t off = (arow + m * 16) * 80 + acolb + ks * 32;
            ldsm4(ah[m][0], ah[m][1], ah[m][2], ah[m][3], Ah + off);
            ldsm4(al2[m][0], al2[m][1], al2[m][2], al2[m][3], Al + off);
        }
        #pragma unroll
        for (int p = 0; p < 4; p++) {
            uint32_t h0, h1, h2, h3, l0, l1, l2, l3;
            if (TRANSB) {
                uint32_t krow = (lane & 7) + ((lane >> 3) & 1) * 8 + ks * 16;
                uint32_t ncol = warpN * 64 + p * 16 + ((lane >> 4) & 1) * 8;
                uint32_t off = krow * 272 + ncol * 2;
                ldsm4t(h0, h1, h2, h3, Bh + off);
                ldsm4t(l0, l1, l2, l3, Bl + off);
            } else {
                uint32_t nrow = warpN * 64 + p * 16 + (lane & 7) + ((lane >> 4) & 1) * 8;
                uint32_t kcol = ks * 16 + ((lane >> 3) & 1) * 8;
                uint32_t off = nrow * 80 + kcol * 2;
                ldsm4(h0, h1, h2, h3, Bh + off);
                ldsm4(l0, l1, l2, l3, Bl + off);
            }
            #pragma unroll
            for (int m = 0; m < 2; m++) {
                float* c0 = acc[m * 8 + 2 * p];
                float* c1 = acc[m * 8 + 2 * p + 1];
                mma16816(c0, ah[m][0], ah[m][1], ah[m][2], ah[m][3], h0, h1);
                mma16816(c0, ah[m][0], ah[m][1], ah[m][2], ah[m][3], l0, l1);
                mma16816(c0, al2[m][0], al2[m][1], al2[m][2], al2[m][3], h0, h1);
                mma16816(c1, ah[m][0], ah[m][1], ah[m][2], ah[m][3], h2, h3);
                mma16816(c1, ah[m][0], ah[m][1], ah[m][2], ah[m][3], l2, l3);
                mma16816(c1, al2[m][0], al2[m][1], al2[m][2], al2[m][3], h2, h3);
            }
        }
    }
}

// ---------------- kernel 0: elementwise W split ----------------
__global__ void wsplit_kernel(const float* __restrict__ wq, const float* __restrict__ wk,
                              const float* __restrict__ wv) {
    const float* w = blockIdx.y == 0 ? wq : (blockIdx.y == 1 ? wk : wv);
    int i = blockIdx.x * 256 + threadIdx.x;
    float f = w[i];
    bf h = __float2bfloat16(f);
    bf l = __float2bfloat16(f - __bfloat162float(h));
    size_t o = (size_t)blockIdx.y * NE * ND + i;
    g_wh[o] = h; g_wl[o] = l;
}

// ---------------- kernel 1: QKV projection ----------------
__global__ __launch_bounds__(256) void qkv_mma(const float* __restrict__ x,
    const float* __restrict__ bq, const float* __restrict__ bk, const float* __restrict__ bv)
{
    __shared__ __align__(16) bf Ah[128 * 40], Al[128 * 40];
    __shared__ __align__(16) bf Bh[32 * 136], Bl[32 * 136];
    const int tid = threadIdx.x, lane = tid & 31, wid = tid >> 5;
    const int warpM = wid >> 1, warpN = wid & 1;
    const int m0 = blockIdx.x * 128, mat = blockIdx.y;
    const uint32_t uAh = s2u(Ah), uAl = s2u(Al), uBh = s2u(Bh), uBl = s2u(Bl);

    float acc[16][4];
    #pragma unroll
    for (int i = 0; i < 16; i++)
        #pragma unroll
        for (int j = 0; j < 4; j++) acc[i][j] = 0.f;

    const int arow = tid >> 1, acol = (tid & 1) * 16;     // 16 floats per thread
    const int brow = tid >> 3, bcol = (tid & 7) * 16;     // 16 bf16 = 2 uint4 per split
    const float* gA = x + (size_t)(m0 + arow) * NE + acol;
    const bf* gBh = g_wh + ((size_t)mat * NE + brow) * ND + bcol;
    const bf* gBl = g_wl + ((size_t)mat * NE + brow) * ND + bcol;

    float4 fA[4];
    uint4 vBh[2], vBl[2];
    #pragma unroll
    for (int i = 0; i < 4; i++) fA[i] = ((const float4*)gA)[i];
    #pragma unroll
    for (int v = 0; v < 2; v++) { vBh[v] = ((const uint4*)gBh)[v]; vBl[v] = ((const uint4*)gBl)[v]; }

    for (int c = 0; c < 32; c++) {
        __syncthreads();
        #pragma unroll
        for (int i = 0; i < 4; i++) {
            uint32_t H0, L0, H1, L1;
            split2(fA[i].x, fA[i].y, H0, L0);
            split2(fA[i].z, fA[i].w, H1, L1);
            uint32_t off = (arow * 40 + acol + i * 4) * 2;
            *(uint2*)((char*)Ah + off) = make_uint2(H0, H1);
            *(uint2*)((char*)Al + off) = make_uint2(L0, L1);
        }
        #pragma unroll
        for (int v = 0; v < 2; v++) {
            *(uint4*)((char*)Bh + (brow * 136 + bcol) * 2 + v * 16) = vBh[v];
            *(uint4*)((char*)Bl + (brow * 136 + bcol) * 2 + v * 16) = vBl[v];
        }
        __syncthreads();
        if (c + 1 < 32) {
            const float* gA2 = gA + (c + 1) * 32;
            #pragma unroll
            for (int i = 0; i < 4; i++) fA[i] = ((const float4*)gA2)[i];
            #pragma unroll
            for (int v = 0; v < 2; v++) {
                vBh[v] = ((const uint4*)(gBh + (size_t)(c + 1) * 32 * ND))[v];
                vBl[v] = ((const uint4*)(gBl + (size_t)(c + 1) * 32 * ND))[v];
            }
        }
        compute_chunk<1>(acc, uAh, uAl, uBh, uBl, lane, warpM, warpN);
    }

    const float* bias = mat == 0 ? bq : (mat == 1 ? bk : bv);
    bf* oh = mat == 0 ? g_qh : (mat == 1 ? g_kh : g_vh);
    bf* ol = mat == 0 ? g_ql : (mat == 1 ? g_kl : g_vl);
    #pragma unroll
    for (int m = 0; m < 2; m++)
        #pragma unroll
        for (int n = 0; n < 8; n++) {
            int row = m0 + warpM * 32 + m * 16 + (lane >> 2);
            int col = warpN * 64 + n * 8 + 2 * (lane & 3);
            float b0 = __ldg(bias + col), b1 = __ldg(bias + col + 1);
            uint32_t H, L;
            split2(acc[m * 8 + n][0] + b0, acc[m * 8 + n][1] + b1, H, L);
            *(uint32_t*)(oh + (size_t)row * ND + col) = H;
            *(uint32_t*)(ol + (size_t)row * ND + col) = L;
            split2(acc[m * 8 + n][2] + b0, acc[m * 8 + n][3] + b1, H, L);
            *(uint32_t*)(oh + (size_t)(row + 8) * ND + col) = H;
            *(uint32_t*)(ol + (size_t)(row + 8) * ND + col) = L;
        }
}

// ---------------- kernel 2: scores = scale * Q.K^T, causal ----------------
__global__ __launch_bounds__(256) void scores_mma()
{
    __shared__ __align__(16) bf Ah[128 * 40], Al[128 * 40];
    __shared__ __align__(16) bf Bh[128 * 40], Bl[128 * 40];
    const int tid = threadIdx.x, lane = tid & 31, wid = tid >> 5;
    const int warpM = wid >> 1, warpN = wid & 1;
    int bi, bj; tri_decode(blockIdx.x, bi, bj);
    const int b = blockIdx.y, i0 = bi * 128, j0 = bj * 128;
    const uint32_t uAh = s2u(Ah), uAl = s2u(Al), uBh = s2u(Bh), uBl = s2u(Bl);

    float acc[16][4];
    #pragma unroll
    for (int i = 0; i < 16; i++)
        #pragma unroll
        for (int j = 0; j < 4; j++) acc[i][j] = 0.f;

    const int arow = tid >> 1, acol = (tid & 1) * 16;
    const bf* gqh = g_qh + (size_t)(b * NS + i0 + arow) * ND + acol;
    const bf* gql = g_ql + (size_t)(b * NS + i0 + arow) * ND + acol;
    const bf* gkh = g_kh + (size_t)(b * NS + j0 + arow) * ND + acol;
    const bf* gkl = g_kl + (size_t)(b * NS + j0 + arow) * ND + acol;

    uint4 sA[2][2], sB[2][2];
    #pragma unroll
    for (int v = 0; v < 2; v++) {
        sA[0][v] = ((const uint4*)gqh)[v]; sA[1][v] = ((const uint4*)gql)[v];
        sB[0][v] = ((const uint4*)gkh)[v]; sB[1][v] = ((const uint4*)gkl)[v];
    }

    for (int c = 0; c < 4; c++) {
        __syncthreads();
        uint32_t off = (arow * 40 + acol) * 2;
        #pragma unroll
        for (int v = 0; v < 2; v++) {
            *(uint4*)((char*)Ah + off + v * 16) = sA[0][v];
            *(uint4*)((char*)Al + off + v * 16) = sA[1][v];
            *(uint4*)((char*)Bh + off + v * 16) = sB[0][v];
            *(uint4*)((char*)Bl + off + v * 16) = sB[1][v];
        }
        __syncthreads();
        if (c + 1 < 4) {
            int d = (c + 1) * 32;
            #pragma unroll
            for (int v = 0; v < 2; v++) {
                sA[0][v] = ((const uint4*)(gqh + d))[v]; sA[1][v] = ((const uint4*)(gql + d))[v];
                sB[0][v] = ((const uint4*)(gkh + d))[v]; sB[1][v] = ((const uint4*)(gkl + d))[v];
            }
        }
        compute_chunk<0>(acc, uAh, uAl, uBh, uBl, lane, warpM, warpN);
    }

    float* sout = g_s + ((size_t)b << 22);
    const float scale = 0.08838834764831845f;
    #pragma unroll
    for (int m = 0; m < 2; m++)
        #pragma unroll
        for (int n = 0; n < 8; n++) {
            int gi = i0 + warpM * 32 + m * 16 + (lane >> 2);
            int gj = j0 + warpN * 64 + n * 8 + 2 * (lane & 3);
            float2 v0, v1;
            v0.x = (gj     <= gi) ? acc[m * 8 + n][0] * scale : -INFINITY;
            v0.y = (gj + 1 <= gi) ? acc[m * 8 + n][1] * scale : -INFINITY;
            v1.x = (gj     <= gi + 8) ? acc[m * 8 + n][2] * scale : -INFINITY;
            v1.y = (gj + 1 <= gi + 8) ? acc[m * 8 + n][3] * scale : -INFINITY;
            *(float2*)(sout + (size_t)gi * NS + gj) = v0;
            *(float2*)(sout + (size_t)(gi + 8) * NS + gj) = v1;
        }
}

// ---------------- kernel 3: softmax -> split-bf16 P ----------------
__global__ __launch_bounds__(256) void softmax_kernel() {
    __shared__ float buf[2048];
    __shared__ float red[8];
    const int rrow = blockIdx.x;
    const int b = rrow >> 11, i = rrow & 2047;
    const float* s = g_s + ((size_t)b << 22) + (size_t)i * NS;
    const size_t prow = (size_t)rrow * NS;
    const int Lp = ((i >> 7) + 1) << 7;
    const int tid = threadIdx.x, lane = tid & 31, wid = tid >> 5;

    float m = -INFINITY;
    for (int j = tid; j < Lp; j += 256) { float v = s[j]; buf[j] = v; m = fmaxf(m, v); }
    #pragma unroll
    for (int o = 16; o; o >>= 1) m = fmaxf(m, __shfl_xor_sync(0xffffffffu, m, o));
    if (lane == 0) red[wid] = m;
    __syncthreads();
    m = red[0];
    #pragma unroll
    for (int w = 1; w < 8; w++) m = fmaxf(m, red[w]);
    __syncthreads();

    float sum = 0.f;
    for (int j = tid; j < Lp; j += 256) {
        float e = (buf[j] == -INFINITY) ? 0.f : __expf(buf[j] - m);
        buf[j] = e; sum += e;
    }
    #pragma unroll
    for (int o = 16; o; o >>= 1) sum += __shfl_xor_sync(0xffffffffu, sum, o);
    if (lane == 0) red[wid] = sum;
    __syncthreads();
    sum = red[0];
    #pragma unroll
    for (int w = 1; w < 8; w++) sum += red[w];

    const float inv = 1.f / sum;
    for (int j = tid; j < Lp; j += 256) {
        float p = buf[j] * inv;
        bf h = __float2bfloat16(p);
        bf l = __float2bfloat16(p - __bfloat162float(h));
        g_Ph[prow + j] = h; g_Pl[prow + j] = l;
    }
}

// ---------------- kernel 4: out += P_tile . V_tile ----------------
__global__ __launch_bounds__(256) void pv_mma(float* __restrict__ out)
{
    __shared__ __align__(16) bf Ah[128 * 40], Al[128 * 40];
    __shared__ __align__(16) bf Bh[32 * 136], Bl[32 * 136];
    const int tid = threadIdx.x, lane = tid & 31, wid = tid >> 5;
    const int warpM = wid >> 1, warpN = wid & 1;
    int bi, bj; tri_decode(blockIdx.x, bi, bj);
    const int b = blockIdx.y, i0 = bi * 128, j0 = bj * 128;
    const uint32_t uAh = s2u(Ah), uAl = s2u(Al), uBh = s2u(Bh), uBl = s2u(Bl);

    float acc[16][4];
    #pragma unroll
    for (int i = 0; i < 16; i++)
        #pragma unroll
        for (int j = 0; j < 4; j++) acc[i][j] = 0.f;

    const int arow = tid >> 1, acol = (tid & 1) * 16;
    const int brow = tid >> 3, bcol = (tid & 7) * 16;
    const bf* gPh = g_Ph + (size_t)(b * NS + i0 + arow) * NS + j0 + acol;
    const bf* gPl = g_Pl + (size_t)(b * NS + i0 + arow) * NS + j0 + acol;
    const bf* gVh = g_vh + (size_t)(b * NS + j0 + brow) * ND + bcol;
    const bf* gVl = g_vl + (size_t)(b * NS + j0 + brow) * ND + bcol;

    uint4 sA[2][2];
    uint4 vBh[2], vBl[2];
    #pragma unroll
    for (int v = 0; v < 2; v++) {
        sA[0][v] = ((const uint4*)gPh)[v]; sA[1][v] = ((const uint4*)gPl)[v];
        vBh[v] = ((const uint4*)gVh)[v];   vBl[v] = ((const uint4*)gVl)[v];
    }

    for (int c = 0; c < 4; c++) {
        __syncthreads();
        uint32_t off = (arow * 40 + acol) * 2;
        #pragma unroll
        for (int v = 0; v < 2; v++) {
            *(uint4*)((char*)Ah + off + v * 16) = sA[0][v];
            *(uint4*)((char*)Al + off + v * 16) = sA[1][v];
            *(uint4*)((char*)Bh + (brow * 136 + bcol) * 2 + v * 16) = vBh[v];
            *(uint4*)((char*)Bl + (brow * 136 + bcol) * 2 + v * 16) = vBl[v];
        }
        __syncthreads();
        if (c + 1 < 4) {
            int d = (c + 1) * 32;
            #pragma unroll
            for (int v = 0; v < 2; v++) {
                sA[0][v] = ((const uint4*)(gPh + d))[v];
                sA[1][v] = ((const uint4*)(gPl + d))[v];
                vBh[v] = ((const uint4*)(gVh + (size_t)(c + 1) * 32 * ND))[v];
                vBl[v] = ((const uint4*)(gVl + (size_t)(c + 1) * 32 * ND))[v];
            }
        }
        compute_chunk<1>(acc, uAh, uAl, uBh, uBl, lane, warpM, warpN);
    }

    #pragma unroll
    for (int m = 0; m < 2; m++)
        #pragma unroll
        for (int n = 0; n < 8; n++) {
            int gi = i0 + warpM * 32 + m * 16 + (lane >> 2);
            int gj = warpN * 64 + n * 8 + 2 * (lane & 3);
            float* o0 = out + (size_t)(b * NS + gi) * ND + gj;
            float* o1 = out + (size_t)(b * NS + gi + 8) * ND + gj;
            atomicAdd(o0,     acc[m * 8 + n][0]);
            atomicAdd(o0 + 1, acc[m * 8 + n][1]);
            atomicAdd(o1,     acc[m * 8 + n][2]);
            atomicAdd(o1 + 1, acc[m * 8 + n][3]);
        }
}

// ---------------- launch ----------------
extern "C" void kernel_launch(void* const* d_in, const int* in_sizes, int n_in,
                              void* d_out, int out_size) {
    const float* x  = (const float*)d_in[0];
    const float* wq = (const float*)d_in[1];
    const float* bq = (const float*)d_in[2];
    const float* wk = (const float*)d_in[3];
    const float* bk = (const float*)d_in[4];
    const float* wv = (const float*)d_in[5];
    const float* bv = (const float*)d_in[6];
    float* out = (float*)d_out;

    cudaMemsetAsync(out, 0, (size_t)out_size * sizeof(float));
    wsplit_kernel<<<dim3(NE * ND / 256, 3), 256>>>(wq, wk, wv);
    qkv_mma<<<dim3(64, 3), 256>>>(x, bq, bk, bv);
    scores_mma<<<dim3(136, NB), 256>>>();
    softmax_kernel<<<NB * NS, 256>>>();
    pv_mma<<<dim3(136, NB), 256>>>(out);
}

// round 6
// speedup vs baseline: 2.3372x; 1.1916x over previous
#include <cuda_runtime.h>
#include <cuda_bf16.h>
#include <stdint.h>
#include <math.h>

#define NB 4
#define NS 2048
#define NE 1024
#define ND 128
#define NTOK 8192

typedef __nv_bfloat16 bf;

// ---------------- device scratch (allocation-free) ----------------
__device__ float g_s [(size_t)NTOK * NS];            // 64 MB scores
__device__ bf g_Ph[(size_t)NTOK * NS];
__device__ bf g_Pl[(size_t)NTOK * NS];
__device__ bf g_xh[NTOK * NE], g_xl[NTOK * NE];      // split x
__device__ bf g_qh[NTOK * ND], g_ql[NTOK * ND];
__device__ bf g_kh[NTOK * ND], g_kl[NTOK * ND];
__device__ bf g_vh[NTOK * ND], g_vl[NTOK * ND];      // [tok][d]
__device__ bf g_wh[3 * NE * ND], g_wl[3 * NE * ND];  // [mat][e][d]

// ---------------- helpers ----------------
__device__ __forceinline__ uint32_t s2u(const void* p) {
    uint32_t a;
    asm("{ .reg .u64 t; cvta.to.shared.u64 t, %1; cvt.u32.u64 %0, t; }" : "=r"(a) : "l"(p));
    return a;
}
__device__ __forceinline__ void ldsm4(uint32_t& r0, uint32_t& r1, uint32_t& r2, uint32_t& r3, uint32_t a) {
    asm volatile("ldmatrix.sync.aligned.m8n8.x4.shared.b16 {%0,%1,%2,%3}, [%4];"
        : "=r"(r0), "=r"(r1), "=r"(r2), "=r"(r3) : "r"(a));
}
__device__ __forceinline__ void ldsm4t(uint32_t& r0, uint32_t& r1, uint32_t& r2, uint32_t& r3, uint32_t a) {
    asm volatile("ldmatrix.sync.aligned.m8n8.x4.trans.shared.b16 {%0,%1,%2,%3}, [%4];"
        : "=r"(r0), "=r"(r1), "=r"(r2), "=r"(r3) : "r"(a));
}
__device__ __forceinline__ void mma16816(float* c,
    uint32_t a0, uint32_t a1, uint32_t a2, uint32_t a3, uint32_t b0, uint32_t b1) {
    asm volatile("mma.sync.aligned.m16n8k16.row.col.f32.bf16.bf16.f32 "
        "{%0,%1,%2,%3}, {%4,%5,%6,%7}, {%8,%9}, {%0,%1,%2,%3};"
        : "+f"(c[0]), "+f"(c[1]), "+f"(c[2]), "+f"(c[3])
        : "r"(a0), "r"(a1), "r"(a2), "r"(a3), "r"(b0), "r"(b1));
}
__device__ __forceinline__ void cpa16(uint32_t s, const void* g) {
    asm volatile("cp.async.cg.shared.global [%0], [%1], 16;" :: "r"(s), "l"(g) : "memory");
}
__device__ __forceinline__ void cpa_commit() {
    asm volatile("cp.async.commit_group;" ::: "memory");
}
template<int N> __device__ __forceinline__ void cpa_wait() {
    asm volatile("cp.async.wait_group %0;" :: "n"(N) : "memory");
}
__device__ __forceinline__ void split2(float a, float b, uint32_t& hi, uint32_t& lo) {
    bf ha = __float2bfloat16(a), hb = __float2bfloat16(b);
    bf la = __float2bfloat16(a - __bfloat162float(ha));
    bf lb = __float2bfloat16(b - __bfloat162float(hb));
    __nv_bfloat162 H, L;
    H.x = ha; H.y = hb; L.x = la; L.y = lb;
    hi = *(uint32_t*)&H; lo = *(uint32_t*)&L;
}
__device__ __forceinline__ void tri_decode(int bidx, int& bi, int& bj) {
    int r = (int)((sqrtf(8.f * bidx + 1.f) - 1.f) * 0.5f);
    while ((r + 1) * (r + 2) / 2 <= bidx) r++;
    while (r * (r + 1) / 2 > bidx) r--;
    bi = r; bj = bidx - r * (r + 1) / 2;
}

// Warp-level split-bf16 GEMM over a K=32 span starting at k0 (elements).
// MW: 16-row m-slabs per warp. AS/BS: smem row strides in ELEMENTS.
// TRANSB=0: B tile [n][k] via ldmatrix; TRANSB=1: B tile [k][n] via ldmatrix.trans.
template<int MW, int AS, int BS, int TRANSB>
__device__ __forceinline__ void compute32(float (*acc)[4],
    uint32_t Ah, uint32_t Al, uint32_t Bh, uint32_t Bl,
    int k0, int lane, int warpM, int warpN)
{
    const uint32_t arow = warpM * (MW * 16) + (lane & 15);
    #pragma unroll
    for (int ks = 0; ks < 2; ks++) {
        uint32_t ah[MW][4], al[MW][4];
        #pragma unroll
        for (int m = 0; m < MW; m++) {
            uint32_t off = ((arow + m * 16) * AS + k0 + ks * 16 + ((lane >> 4) & 1) * 8) * 2;
            ldsm4(ah[m][0], ah[m][1], ah[m][2], ah[m][3], Ah + off);
            ldsm4(al[m][0], al[m][1], al[m][2], al[m][3], Al + off);
        }
        #pragma unroll
        for (int p = 0; p < 4; p++) {
            uint32_t h0, h1, h2, h3, l0, l1, l2, l3;
            if (TRANSB) {
                uint32_t off = ((uint32_t)(k0 + ks * 16 + (lane & 15)) * BS
                              + warpN * 64 + p * 16 + ((lane >> 4) & 1) * 8) * 2;
                ldsm4t(h0, h1, h2, h3, Bh + off);
                ldsm4t(l0, l1, l2, l3, Bl + off);
            } else {
                uint32_t off = ((uint32_t)(warpN * 64 + p * 16 + (lane & 7) + ((lane >> 4) & 1) * 8) * BS
                              + k0 + ks * 16 + ((lane >> 3) & 1) * 8) * 2;
                ldsm4(h0, h1, h2, h3, Bh + off);
                ldsm4(l0, l1, l2, l3, Bl + off);
            }
            #pragma unroll
            for (int m = 0; m < MW; m++) {
                float* c0 = acc[m * 8 + 2 * p];
                float* c1 = acc[m * 8 + 2 * p + 1];
                mma16816(c0, ah[m][0], ah[m][1], ah[m][2], ah[m][3], h0, h1);
                mma16816(c0, ah[m][0], ah[m][1], ah[m][2], ah[m][3], l0, l1);
                mma16816(c0, al[m][0], al[m][1], al[m][2], al[m][3], h0, h1);
                mma16816(c1, ah[m][0], ah[m][1], ah[m][2], ah[m][3], h2, h3);
                mma16816(c1, ah[m][0], ah[m][1], ah[m][2], ah[m][3], l2, l3);
                mma16816(c1, al[m][0], al[m][1], al[m][2], al[m][3], h2, h3);
            }
        }
    }
}

// ---------------- prepass: split x and W ----------------
__global__ __launch_bounds__(256) void xsplit_kernel(const float* __restrict__ x) {
    int i = blockIdx.x * 256 + threadIdx.x;          // float4 index
    float4 v = ((const float4*)x)[i];
    uint32_t h0, l0, h1, l1;
    split2(v.x, v.y, h0, l0);
    split2(v.z, v.w, h1, l1);
    ((uint2*)g_xh)[i] = make_uint2(h0, h1);
    ((uint2*)g_xl)[i] = make_uint2(l0, l1);
}
__global__ __launch_bounds__(256) void wsplit_kernel(const float* __restrict__ wq,
    const float* __restrict__ wk, const float* __restrict__ wv) {
    const float* w = blockIdx.y == 0 ? wq : (blockIdx.y == 1 ? wk : wv);
    int i = blockIdx.x * 256 + threadIdx.x;
    float f = w[i];
    bf h = __float2bfloat16(f);
    bf l = __float2bfloat16(f - __bfloat162float(h));
    size_t o = (size_t)blockIdx.y * NE * ND + i;
    g_wh[o] = h; g_wl[o] = l;
}

// ---------------- kernel 1: QKV projection (M64, cp.async 3-stage) ----------------
// grid (128, 3). A = split x (AS=40), B = W[e][d] TRANSB (BS=136).
#define QKV_STAGE 27648u
__global__ __launch_bounds__(256) void qkv_mma(
    const float* __restrict__ bq, const float* __restrict__ bk, const float* __restrict__ bv)
{
    extern __shared__ __align__(16) char sm[];
    const uint32_t sb = s2u(sm);
    const int tid = threadIdx.x, lane = tid & 31, wid = tid >> 5;
    const int warpM = wid >> 1, warpN = wid & 1;
    const int m0 = blockIdx.x * 64, mat = blockIdx.y;

    float acc[8][4];
    #pragma unroll
    for (int i = 0; i < 8; i++)
        #pragma unroll
        for (int j = 0; j < 4; j++) acc[i][j] = 0.f;

    auto load_stage = [&](int st, int kb) {
        uint32_t stg = sb + st * QKV_STAGE;
        #pragma unroll
        for (int i = 0; i < 2; i++) {                 // A: 64 rows x 4 segs x2
            int sidx = tid + i * 256;
            int split = sidx >> 8, r = (sidx & 255) >> 2, seg = sidx & 3;
            const bf* src = (split ? g_xl : g_xh) + (size_t)(m0 + r) * NE + kb + seg * 8;
            cpa16(stg + split * 5120 + r * 80 + seg * 16, src);
        }
        #pragma unroll
        for (int i = 0; i < 4; i++) {                 // B: 32 rows x 16 segs x2
            int sidx = tid + i * 256;
            int split = sidx >> 9, r = (sidx & 511) >> 4, seg = sidx & 15;
            const bf* src = (split ? g_wl : g_wh) + ((size_t)mat * NE + kb + r) * ND + seg * 8;
            cpa16(stg + 10240 + split * 8704 + r * 272 + seg * 16, src);
        }
        cpa_commit();
    };

    load_stage(0, 0);
    load_stage(1, 32);
    for (int c = 0; c < 32; c++) {
        if (c >= 31) cpa_wait<0>(); else cpa_wait<1>();
        __syncthreads();
        uint32_t stg = sb + (uint32_t)(c % 3) * QKV_STAGE;
        compute32<1, 40, 136, 1>(acc, stg, stg + 5120, stg + 10240, stg + 10240 + 8704,
                                 0, lane, warpM, warpN);
        if (c + 2 < 32) load_stage((c + 2) % 3, (c + 2) * 32);
    }

    const float* bias = mat == 0 ? bq : (mat == 1 ? bk : bv);
    bf* oh = mat == 0 ? g_qh : (mat == 1 ? g_kh : g_vh);
    bf* ol = mat == 0 ? g_ql : (mat == 1 ? g_kl : g_vl);
    const int row = m0 + warpM * 16 + (lane >> 2);
    #pragma unroll
    for (int n = 0; n < 8; n++) {
        int col = warpN * 64 + n * 8 + 2 * (lane & 3);
        float b0 = __ldg(bias + col), b1 = __ldg(bias + col + 1);
        uint32_t H, L;
        split2(acc[n][0] + b0, acc[n][1] + b1, H, L);
        *(uint32_t*)(oh + (size_t)row * ND + col) = H;
        *(uint32_t*)(ol + (size_t)row * ND + col) = L;
        split2(acc[n][2] + b0, acc[n][3] + b1, H, L);
        *(uint32_t*)(oh + (size_t)(row + 8) * ND + col) = H;
        *(uint32_t*)(ol + (size_t)(row + 8) * ND + col) = L;
    }
}

// ---------------- kernel 2: scores (M64, full-K resident, 2 async groups) ----------------
// grid (136, 4, 2). A = Q rows 64, B = K tile [n=128][k=128], both AS=BS=136.
__global__ __launch_bounds__(256) void scores_mma()
{
    extern __shared__ __align__(16) char sm[];
    const uint32_t sb = s2u(sm);
    const int tid = threadIdx.x, lane = tid & 31, wid = tid >> 5;
    const int warpM = wid >> 1, warpN = wid & 1;
    int bi, bj; tri_decode(blockIdx.x, bi, bj);
    const int b = blockIdx.y, i0 = bi * 128 + blockIdx.z * 64, j0 = bj * 128;

    float acc[8][4];
    #pragma unroll
    for (int i = 0; i < 8; i++)
        #pragma unroll
        for (int j = 0; j < 4; j++) acc[i][j] = 0.f;

    const size_t qbase = (size_t)(b * NS + i0) * ND;
    const size_t kbase = (size_t)(b * NS + j0) * ND;

    auto load_group = [&](int kb) {
        #pragma unroll
        for (int i = 0; i < 4; i++) {                 // A: 64 rows x 8 segs x2
            int sidx = tid + i * 256;
            int split = sidx >> 9, r = (sidx & 511) >> 3, seg = sidx & 7;
            const bf* src = (split ? g_ql : g_qh) + qbase + (size_t)r * ND + kb + seg * 8;
            cpa16(sb + split * 17408 + r * 272 + (kb + seg * 8) * 2, src);
        }
        #pragma unroll
        for (int i = 0; i < 8; i++) {                 // B: 128 rows x 8 segs x2
            int sidx = tid + i * 256;
            int split = sidx >> 10, r = (sidx & 1023) >> 3, seg = sidx & 7;
            const bf* src = (split ? g_kl : g_kh) + kbase + (size_t)r * ND + kb + seg * 8;
            cpa16(sb + 34816 + split * 34816 + r * 272 + (kb + seg * 8) * 2, src);
        }
        cpa_commit();
    };
    load_group(0);
    load_group(64);
    cpa_wait<1>(); __syncthreads();
    compute32<1, 136, 136, 0>(acc, sb, sb + 17408, sb + 34816, sb + 69632,  0, lane, warpM, warpN);
    compute32<1, 136, 136, 0>(acc, sb, sb + 17408, sb + 34816, sb + 69632, 32, lane, warpM, warpN);
    cpa_wait<0>(); __syncthreads();
    compute32<1, 136, 136, 0>(acc, sb, sb + 17408, sb + 34816, sb + 69632, 64, lane, warpM, warpN);
    compute32<1, 136, 136, 0>(acc, sb, sb + 17408, sb + 34816, sb + 69632, 96, lane, warpM, warpN);

    float* sout = g_s + ((size_t)b << 22);
    const float scale = 0.08838834764831845f;
    const int gi = i0 + warpM * 16 + (lane >> 2);
    #pragma unroll
    for (int n = 0; n < 8; n++) {
        int gj = j0 + warpN * 64 + n * 8 + 2 * (lane & 3);
        float2 v0, v1;
        v0.x = (gj     <= gi) ? acc[n][0] * scale : -INFINITY;
        v0.y = (gj + 1 <= gi) ? acc[n][1] * scale : -INFINITY;
        v1.x = (gj     <= gi + 8) ? acc[n][2] * scale : -INFINITY;
        v1.y = (gj + 1 <= gi + 8) ? acc[n][3] * scale : -INFINITY;
        *(float2*)(sout + (size_t)gi * NS + gj) = v0;
        *(float2*)(sout + (size_t)(gi + 8) * NS + gj) = v1;
    }
}

// ---------------- kernel 3: softmax -> split-bf16 P (vectorized) ----------------
__global__ __launch_bounds__(256) void softmax_kernel() {
    __shared__ __align__(16) float buf[2048];
    __shared__ float red[8];
    const int rrow = blockIdx.x;
    const int b = rrow >> 11, i = rrow & 2047;
    const float4* s4 = (const float4*)(g_s + ((size_t)b << 22) + (size_t)i * NS);
    const int n4 = (((i >> 7) + 1) << 7) >> 2;        // Lp/4
    const int tid = threadIdx.x, lane = tid & 31, wid = tid >> 5;
    float4* b4 = (float4*)buf;

    float m = -INFINITY;
    for (int j = tid; j < n4; j += 256) {
        float4 v = s4[j]; b4[j] = v;
        m = fmaxf(m, fmaxf(fmaxf(v.x, v.y), fmaxf(v.z, v.w)));
    }
    #pragma unroll
    for (int o = 16; o; o >>= 1) m = fmaxf(m, __shfl_xor_sync(0xffffffffu, m, o));
    if (lane == 0) red[wid] = m;
    __syncthreads();
    m = red[0];
    #pragma unroll
    for (int w = 1; w < 8; w++) m = fmaxf(m, red[w]);
    __syncthreads();

    float sum = 0.f;
    for (int j = tid; j < n4; j += 256) {
        float4 v = b4[j];
        v.x = __expf(v.x - m); v.y = __expf(v.y - m);
        v.z = __expf(v.z - m); v.w = __expf(v.w - m);
        b4[j] = v;
        sum += (v.x + v.y) + (v.z + v.w);
    }
    #pragma unroll
    for (int o = 16; o; o >>= 1) sum += __shfl_xor_sync(0xffffffffu, sum, o);
    if (lane == 0) red[wid] = sum;
    __syncthreads();
    sum = red[0];
    #pragma unroll
    for (int w = 1; w < 8; w++) sum += red[w];

    const float inv = 1.f / sum;
    uint2* ph = (uint2*)(g_Ph + (size_t)rrow * NS);
    uint2* pl = (uint2*)(g_Pl + (size_t)rrow * NS);
    for (int j = tid; j < n4; j += 256) {
        float4 v = b4[j];
        uint32_t h0, l0, h1, l1;
        split2(v.x * inv, v.y * inv, h0, l0);
        split2(v.z * inv, v.w * inv, h1, l1);
        ph[j] = make_uint2(h0, h1);
        pl[j] = make_uint2(l0, l1);
    }
}

// ---------------- kernel 4: P.V (M64, full-K resident, 2 async groups) ----------------
// grid (136, 4, 2). A = P rows 64 (AS=136), B = V [k=128][n=128] TRANSB (BS=136).
__global__ __launch_bounds__(256) void pv_mma(float* __restrict__ out)
{
    extern __shared__ __align__(16) char sm[];
    const uint32_t sb = s2u(sm);
    const int tid = threadIdx.x, lane = tid & 31, wid = tid >> 5;
    const int warpM = wid >> 1, warpN = wid & 1;
    int bi, bj; tri_decode(blockIdx.x, bi, bj);
    const int b = blockIdx.y, i0 = bi * 128 + blockIdx.z * 64, j0 = bj * 128;

    float acc[8][4];
    #pragma unroll
    for (int i = 0; i < 8; i++)
        #pragma unroll
        for (int j = 0; j < 4; j++) acc[i][j] = 0.f;

    const size_t pbase = (size_t)(b * NS + i0) * NS + j0;
    const size_t vbase = (size_t)(b * NS + j0) * ND;

    auto load_group = [&](int kb) {
        #pragma unroll
        for (int i = 0; i < 4; i++) {                 // A: 64 rows x 8 segs x2
            int sidx = tid + i * 256;
            int split = sidx >> 9, r = (sidx & 511) >> 3, seg = sidx & 7;
            const bf* src = (split ? g_Pl : g_Ph) + pbase + (size_t)r * NS + kb + seg * 8;
            cpa16(sb + split * 17408 + r * 272 + (kb + seg * 8) * 2, src);
        }
        #pragma unroll
        for (int i = 0; i < 8; i++) {                 // B: 64 k-rows x 16 segs x2
            int sidx = tid + i * 256;
            int split = sidx >> 10, r = (sidx & 1023) >> 4, seg = sidx & 15;
            const bf* src = (split ? g_vl : g_vh) + vbase + (size_t)(kb + r) * ND + seg * 8;
            cpa16(sb + 34816 + split * 34816 + (kb + r) * 272 + seg * 16, src);
        }
        cpa_commit();
    };
    load_group(0);
    load_group(64);
    cpa_wait<1>(); __syncthreads();
    compute32<1, 136, 136, 1>(acc, sb, sb + 17408, sb + 34816, sb + 69632,  0, lane, warpM, warpN);
    compute32<1, 136, 136, 1>(acc, sb, sb + 17408, sb + 34816, sb + 69632, 32, lane, warpM, warpN);
    cpa_wait<0>(); __syncthreads();
    compute32<1, 136, 136, 1>(acc, sb, sb + 17408, sb + 34816, sb + 69632, 64, lane, warpM, warpN);
    compute32<1, 136, 136, 1>(acc, sb, sb + 17408, sb + 34816, sb + 69632, 96, lane, warpM, warpN);

    const int gi = i0 + warpM * 16 + (lane >> 2);
    #pragma unroll
    for (int n = 0; n < 8; n++) {
        int gj = warpN * 64 + n * 8 + 2 * (lane & 3);
        float* o0 = out + (size_t)(b * NS + gi) * ND + gj;
        float* o1 = out + (size_t)(b * NS + gi + 8) * ND + gj;
        atomicAdd(o0,     acc[n][0]);
        atomicAdd(o0 + 1, acc[n][1]);
        atomicAdd(o1,     acc[n][2]);
        atomicAdd(o1 + 1, acc[n][3]);
    }
}

// ---------------- launch ----------------
extern "C" void kernel_launch(void* const* d_in, const int* in_sizes, int n_in,
                              void* d_out, int out_size) {
    const float* x  = (const float*)d_in[0];
    const float* wq = (const float*)d_in[1];
    const float* bq = (const float*)d_in[2];
    const float* wk = (const float*)d_in[3];
    const float* bk = (const float*)d_in[4];
    const float* wv = (const float*)d_in[5];
    const float* bv = (const float*)d_in[6];
    float* out = (float*)d_out;

    static int inited = 0;
    if (!inited) {
        cudaFuncSetAttribute(qkv_mma,    cudaFuncAttributeMaxDynamicSharedMemorySize, 3 * QKV_STAGE);
        cudaFuncSetAttribute(scores_mma, cudaFuncAttributeMaxDynamicSharedMemorySize, 104448);
        cudaFuncSetAttribute(pv_mma,     cudaFuncAttributeMaxDynamicSharedMemorySize, 104448);
        inited = 1;
    }

    cudaMemsetAsync(out, 0, (size_t)out_size * sizeof(float));
    xsplit_kernel<<<NTOK * NE / 1024, 256>>>(x);
    wsplit_kernel<<<dim3(NE * ND / 256, 3), 256>>>(wq, wk, wv);
    qkv_mma<<<dim3(128, 3), 256, 3 * QKV_STAGE>>>(bq, bk, bv);
    scores_mma<<<dim3(136, NB, 2), 256, 104448>>>();
    softmax_kernel<<<NB * NS, 256>>>();
    pv_mma<<<dim3(136, NB, 2), 256, 104448>>>(out);
}